// round 17
// baseline (speedup 1.0000x reference)
#include <cuda_runtime.h>
#include <cuda_bf16.h>

// NeuSSampler inverse-CDF importance sampling — v17: thread-per-ray
// sequential merge. weights [R,128,1] f32, existing_bins [R,129] f32,
// nears [R,1], fars [R,1] -> out [R,65] f32.
//
// CDF (in s) and queries u_j (uniform grid) are both monotone ->
// inverse-CDF is a single linear merge: 128 advances + 65 emits per ray,
// no search. One ray per THREAD (32 rays per warp instruction).
// All global traffic is coalesced via smem staging:
//   ebins: block's 128 rays are contiguous -> linear float4 copy
//          (stride-129 smem rows: 129 % 32 == 1 -> conflict-free reads).
//   weights: chunked 16-sample tiles, stride-19 rows; read twice from
//          global (2nd pass hits L2: 19MB working set << 126MB L2).
//   out:   staged in smem, one contiguous coalesced block copy.
// Queries compared in UNNORMALIZED space (u scaled by padded total);
// the lerp ratio t is scale-invariant, so no per-element normalization.

#define S_SAMP 128
#define NB 65
#define HIST_PAD 1e-5f
#define EPS_V 1e-5f
#define THREADS 128
#define RPB 128                 // rays per block (= THREADS)
#define CH 16                   // samples per weight chunk
#define NCH (S_SAMP / CH)       // 8 chunks
#define WSTRIDE 19              // wt row stride (odd -> conflict-free)

// smem layout (floats):  eb[128*129] | stag[128*65] | wt[128*19]
#define EB_F   (RPB * 129)              // 16512
#define STAG_F (RPB * NB)               // 8320
#define WT_F   (RPB * WSTRIDE)          // 2432
#define SMEM_BYTES ((EB_F + STAG_F + WT_F) * 4)   // 109056

__global__ __launch_bounds__(THREADS, 2)
void neus_sampler_kernel(const float* __restrict__ weights,
                         const float* __restrict__ ebins,
                         const float* __restrict__ nears,
                         const float* __restrict__ fars,
                         float* __restrict__ out,
                         int R)
{
    extern __shared__ float sm[];
    float* eb_s = sm;                       // [ray][129] contiguous
    float* stag = sm + EB_F;                // [ray][65]  contiguous
    float* wt   = sm + EB_F + STAG_F;       // [row][19]

    const int tid = threadIdx.x;
    const unsigned rayBase = blockIdx.x * RPB;
    const int nrays = min(RPB, R - (int)rayBase);   // partial-block guard
    const int myrow = min(tid, nrays - 1);          // clamped own ray
    const unsigned ray = rayBase + myrow;

    // ---- E. ebins block copy: contiguous region, linear float4 ----
    {
        const float4* src =
            reinterpret_cast<const float4*>(ebins + rayBase * 129u);
        float4* dst = reinterpret_cast<float4*>(eb_s);
        const int n4 = (nrays * 129 + 3) >> 2;      // <= 4128
        for (int i = tid; i < n4; i += THREADS) dst[i] = src[i];
    }

    const float4* wg4 =
        reinterpret_cast<const float4*>(weights + rayBase * 128u);
    const int rmax = nrays - 1;

    // ---- W1. per-ray totals (chunked through smem transpose) ----
    float tot = 0.0f;
    for (int c = 0; c < NCH; c++) {
        __syncthreads();
        #pragma unroll
        for (int kk = 0; kk < 4; kk++) {
            const int idx = tid + kk * THREADS;     // 0..511
            const int r = idx >> 2, q = idx & 3;
            const float4 v = wg4[min(r, rmax) * 32 + c * 4 + q];
            float* d = wt + r * WSTRIDE + q * 4;
            d[0] = v.x; d[1] = v.y; d[2] = v.z; d[3] = v.w;
        }
        __syncthreads();
        const float* wr = wt + myrow * WSTRIDE;
        #pragma unroll
        for (int s = 0; s < CH; s++) tot += wr[s];
    }

    // ---- padding fold + scaled-query constants ----
    const float total_wp  = tot + (float)S_SAMP * HIST_PAD;
    const float padding   = fmaxf(0.0f, EPS_V - total_wp);
    const float total_eff = total_wp + padding;
    const float step      = HIST_PAD + padding * (1.0f / (float)S_SAMP);
    const float du        = total_eff * (1.0f / (float)NB);
    float us = 0.5f * du;

    const float nearv = nears[ray];
    const float dfn   = fars[ray] - nearv;
    const float* ebr  = eb_s + myrow * 129;
    float* str        = stag + myrow * NB;

    float cum = 0.0f;
    int jj = 0;

    // ---- M. sequential merge: 128 advances + 65 emits ----
    for (int c = 0; c < NCH; c++) {
        __syncthreads();
        #pragma unroll
        for (int kk = 0; kk < 4; kk++) {
            const int idx = tid + kk * THREADS;
            const int r = idx >> 2, q = idx & 3;
            const float4 v = wg4[min(r, rmax) * 32 + c * 4 + q];
            float* d = wt + r * WSTRIDE + q * 4;
            d[0] = v.x; d[1] = v.y; d[2] = v.z; d[3] = v.w;
        }
        __syncthreads();

        const float* wr  = wt + myrow * WSTRIDE;
        const float* ebc = ebr + c * CH;
        int s_loc = 0;
        float cum_next = cum + (wr[0] + step);
        float w_next   = wr[1];
        while (s_loc < CH) {
            if (us < cum_next) {                     // emit at segment s
                const float t   = __fdividef(us - cum, cum_next - cum);
                const float blo = ebc[s_loc];
                const float bhi = ebc[s_loc + 1];
                const float bb  = fmaf(t, bhi - blo, blo);
                str[jj] = fmaf(bb, dfn, nearv);
                jj++; us += du;
            } else {                                 // advance s
                cum = cum_next;
                s_loc++;
                cum_next = cum + (w_next + step);
                w_next = wr[s_loc + 1];              // <= wr[17], in-bounds
            }
        }
    }
    // rounding-tie tail: t -> 1 limit == ebins[128] value
    {
        const float tailv = fmaf(ebr[128], dfn, nearv);
        while (jj < NB) { str[jj] = tailv; jj++; }
    }

    // ---- O. coalesced writeout of the contiguous staging block ----
    __syncthreads();
    {
        const float4* s4 = reinterpret_cast<const float4*>(stag);
        float4* o4 = reinterpret_cast<float4*>(out + rayBase * 65u);
        const int n4 = (nrays * NB + 3) >> 2;        // <= 2080
        for (int i = tid; i < n4; i += THREADS) o4[i] = s4[i];
    }
}

extern "C" void kernel_launch(void* const* d_in, const int* in_sizes, int n_in,
                              void* d_out, int out_size) {
    const float* weights = (const float*)d_in[0];
    const float* ebins   = (const float*)d_in[1];
    const float* nears   = (const float*)d_in[2];
    const float* fars    = (const float*)d_in[3];
    float* out = (float*)d_out;

    const int R = in_sizes[2];  // nears has R elements

    static int configured = 0;   // idempotent attribute set (not a stream op)
    if (!configured) {
        cudaFuncSetAttribute(neus_sampler_kernel,
                             cudaFuncAttributeMaxDynamicSharedMemorySize,
                             SMEM_BYTES);
        configured = 1;
    }

    const int grid = (R + RPB - 1) / RPB;
    neus_sampler_kernel<<<grid, THREADS, SMEM_BYTES>>>(
        weights, ebins, nears, fars, out, R);
}